// round 1
// baseline (speedup 1.0000x reference)
#include <cuda_runtime.h>
#include <math.h>

// Problem shape (fixed by setup_inputs)
#define BB   8
#define HH   256
#define WW   256
#define NPIX (BB * HH * WW)

// Scratch: squared vertical distance, per-batch nonempty flag, 5 global sums.
// sums order: [0]=ce, [1]=sum_p, [2]=sum_t, [3]=sum_p*t, [4]=sum_p*dt
__device__ float  g_g2[NPIX];
__device__ int    g_nonempty[BB];
__device__ double g_sums[5];

// ---------------------------------------------------------------------------
__global__ void k_init() {
    int i = threadIdx.x;
    if (i < 5)  g_sums[i] = 0.0;
    if (i < BB) g_nonempty[i] = 0;
}

// ---------------------------------------------------------------------------
// Vertical pass: per (batch, column) thread. Forward scan stores running
// distance; backward scan mins, squares, and stores g^2.
__global__ void k_vert(const float* __restrict__ target) {
    int b   = blockIdx.x;           // 0..7
    int col = threadIdx.x;          // 0..255
    const float* t = target + b * HH * WW;
    float* g2 = g_g2 + b * HH * WW;

    const float INF = (float)(HH + WW);   // 512, matches reference
    float d = INF;
    int any = 0;

    // top-down
    for (int i = 0; i < HH; i++) {
        bool fg = t[i * WW + col] > 0.5f;
        if (fg) { d = 0.0f; any = 1; } else { d += 1.0f; }
        g2[i * WW + col] = d;
    }
    // bottom-up, combine, square
    d = INF;
    for (int i = HH - 1; i >= 0; i--) {
        bool fg = t[i * WW + col] > 0.5f;
        if (fg) d = 0.0f; else d += 1.0f;
        float m = fminf(d, g2[i * WW + col]);
        g2[i * WW + col] = m * m;
    }
    if (any) atomicOr(&g_nonempty[b], 1);
}

// ---------------------------------------------------------------------------
__device__ __forceinline__ float warp_sum(float v) {
    #pragma unroll
    for (int o = 16; o > 0; o >>= 1)
        v += __shfl_xor_sync(0xffffffffu, v, o);
    return v;
}

// Main fused kernel: one block per (b, row). Exact horizontal EDT pass over
// shared g^2 row (broadcast LDS), then per-element CE/sigmoid/dice/boundary
// terms, block reduction, 5 double atomicAdds.
__global__ void __launch_bounds__(WW) k_main(const float* __restrict__ logits,
                                             const float* __restrict__ target) {
    int b   = blockIdx.x / HH;
    int row = blockIdx.x % HH;
    int j   = threadIdx.x;

    __shared__ float s_g2[WW];
    const float* g2row = g_g2 + (b * HH + row) * WW;
    s_g2[j] = g2row[j];
    __syncthreads();

    // dt2[j] = min_k (j-k)^2 + g2[k]
    float best = 3.4e38f;
    float fj = (float)j;        // running (j - k)
    #pragma unroll 8
    for (int k = 0; k < WW; k++) {
        best = fminf(best, fmaf(fj, fj, s_g2[k]));
        fj -= 1.0f;
    }
    float dt = g_nonempty[b] ? sqrtf(best) : 0.0f;

    int idx = (b * HH + row) * WW + j;
    float x = logits[idx];
    float t = fminf(fmaxf(target[idx], 0.0f), 1.0f);

    // logaddexp(0, x) - x*t  (stable)
    float ce_e = fmaxf(x, 0.0f) + log1pf(expf(-fabsf(x))) - x * t;
    float p = 1.0f / (1.0f + expf(-x));
    p = fminf(fmaxf(p, 1e-6f), 1.0f - 1e-6f);

    float vals[5] = { ce_e, p, t, p * t, p * dt };

    __shared__ float red[WW / 32][5];
    int lane = j & 31, warp = j >> 5;
    #pragma unroll
    for (int s = 0; s < 5; s++) {
        float v = warp_sum(vals[s]);
        if (lane == 0) red[warp][s] = v;
    }
    __syncthreads();
    if (warp == 0) {
        #pragma unroll
        for (int s = 0; s < 5; s++) {
            float v = (lane < WW / 32) ? red[lane][s] : 0.0f;
            v = warp_sum(v);
            if (lane == 0) atomicAdd(&g_sums[s], (double)v);
        }
    }
}

// ---------------------------------------------------------------------------
__global__ void k_final(float* __restrict__ out, int out_size) {
    const double N = (double)NPIX;
    const double SMOOTH = 1e-6;
    double ce       = g_sums[0] / N;
    double sum_p    = g_sums[1];
    double sum_t    = g_sums[2];
    double inter    = g_sums[3];
    double sum_pdt  = g_sums[4];
    double dice     = 1.0 - (2.0 * inter + SMOOTH) / (sum_p + sum_t + SMOOTH);
    double boundary = sum_pdt / N;
    double total    = 1.0 * ce + 1.0 * dice + 0.1 * boundary;

    float vals[4] = { (float)total, (float)ce, (float)dice, (float)boundary };
    for (int i = 0; i < out_size && i < 4; i++) out[i] = vals[i];
}

// ---------------------------------------------------------------------------
extern "C" void kernel_launch(void* const* d_in, const int* in_sizes, int n_in,
                              void* d_out, int out_size) {
    const float* logits = (const float*)d_in[0];
    const float* target = (const float*)d_in[1];
    float* out = (float*)d_out;
    (void)in_sizes; (void)n_in;

    k_init<<<1, 32>>>();
    k_vert<<<BB, WW>>>(target);
    k_main<<<BB * HH, WW>>>(logits, target);
    k_final<<<1, 1>>>(out, out_size);
}

// round 4
// speedup vs baseline: 1.2043x; 1.2043x over previous
#include <cuda_runtime.h>
#include <math.h>

// Problem shape (fixed by setup_inputs)
#define BB   8
#define HH   256
#define WW   256
#define NPIX (BB * HH * WW)
#define GRID 296          // 148 SMs x 2 blocks, all co-resident
#define TPB  256

// Persistent scratch. Counters/flags are reset by the finalizer block at the
// end of every launch, so each graph replay starts from a clean state.
__device__ float    g_g2[NPIX];        // squared vertical distance
__device__ int      g_nonempty[BB];
__device__ unsigned g_bar0;            // grid barrier counter
__device__ unsigned g_done;            // completion ticket
__device__ double   g_part[GRID * 5];  // per-block partial sums

__device__ __forceinline__ float warp_sum_f(float v) {
    #pragma unroll
    for (int o = 16; o > 0; o >>= 1) v += __shfl_xor_sync(0xffffffffu, v, o);
    return v;
}

__global__ void __launch_bounds__(TPB, 2)
fused_loss_kernel(const float* __restrict__ logits,
                  const float* __restrict__ target,
                  float* __restrict__ out, int out_size)
{
    const int tid = threadIdx.x;
    const int bid = blockIdx.x;
    const int lane = tid & 31, warp = tid >> 5;

    __shared__ float  s_g2[WW];
    __shared__ float  s_sqrt[128];
    __shared__ float  s_red[TPB / 32];
    __shared__ unsigned s_ticket;

    // sqrt LUT: horizontal EDT "best" is always an exact small integer
    if (tid < 128) s_sqrt[tid] = sqrtf((float)tid);

    // ================= phase 1: vertical EDT (64 warp-tasks) =================
    // blocks 0..63, warp 0: one warp per (batch, 32-column group); coalesced.
    if (bid < 64 && tid < 32) {
        int b   = bid >> 3;
        int col = (bid & 7) * 32 + tid;
        const float* t = target + b * HH * WW;
        float* g2 = g_g2 + b * HH * WW;

        float d = 512.0f;   // INF = H + W, matches reference
        int any = 0;
        for (int i = 0; i < HH; i++) {                 // top-down
            float tv = t[i * WW + col];
            if (tv > 0.5f) { d = 0.0f; any = 1; } else d += 1.0f;
            g2[i * WW + col] = d;
        }
        d = 512.0f;
        for (int i = HH - 1; i >= 0; i--) {            // bottom-up + square
            float tv = t[i * WW + col];
            d = (tv > 0.5f) ? 0.0f : (d + 1.0f);
            float m = fminf(d, g2[i * WW + col]);
            g2[i * WW + col] = m * m;
        }
        unsigned m = __ballot_sync(0xffffffffu, any);
        if (tid == 0 && m) g_nonempty[b] = 1;          // benign same-value race
    }

    // ================= grid barrier (all 296 blocks resident) ================
    __syncthreads();
    __threadfence();
    if (tid == 0) {
        atomicAdd(&g_bar0, 1u);
        while (atomicAdd(&g_bar0, 0u) < gridDim.x) __nanosleep(64);
    }
    __syncthreads();
    __threadfence();

    // ================= phase 2: exact horizontal EDT + fused loss ============
    float acc0 = 0.f, acc1 = 0.f, acc2 = 0.f, acc3 = 0.f, acc4 = 0.f;

    for (int rt = bid; rt < BB * HH; rt += gridDim.x) {
        int b    = rt >> 8;
        int base = rt * WW;   // contiguous layout: (b*HH + row) * WW == rt*WW

        s_g2[tid] = g_g2[base + tid];
        int ne = g_nonempty[b];
        __syncthreads();

        float dt = 0.0f;
        if (ne) {
            // exact: stop when off^2 >= best (all further terms >= best)
            float best = s_g2[tid];
            int off = 1;
            float o2 = 1.0f;
            while (o2 < best) {
                int l = tid - off, r = tid + off;
                if (l >= 0) best = fminf(best, o2 + s_g2[l]);
                if (r < WW) best = fminf(best, o2 + s_g2[r]);
                off++;
                o2 = (float)(off * off);
            }
            dt = (best < 128.0f) ? s_sqrt[(int)best] : sqrtf(best);
        }

        float x = logits[base + tid];
        float t = fminf(fmaxf(target[base + tid], 0.0f), 1.0f);

        // 3 MUFU per pixel: ex2, rcp, lg2
        float ax = fabsf(x);
        float eh = __expf(-ax);                 // e^{-|x|} in (0,1]
        float r  = __fdividef(1.0f, 1.0f + eh); // MUFU rcp
        float p  = (x >= 0.0f) ? r : eh * r;    // sigmoid(x)
        p = fminf(fmaxf(p, 1e-6f), 1.0f - 1e-6f);
        // log1p(eh) = -ln(r) = -ln2 * log2(r)
        float ce = fmaxf(x, 0.0f) - 0.69314718055994531f * __log2f(r) - x * t;

        acc0 += ce; acc1 += p; acc2 += t; acc3 += p * t; acc4 += p * dt;
        __syncthreads();
    }

    // ================= per-block reduction -> g_part (deterministic) =========
    float accs[5] = { acc0, acc1, acc2, acc3, acc4 };
    #pragma unroll
    for (int s = 0; s < 5; s++) {
        float v = warp_sum_f(accs[s]);
        if (lane == 0) s_red[warp] = v;
        __syncthreads();
        if (tid == 0) {
            float tot = 0.f;
            #pragma unroll
            for (int w = 0; w < TPB / 32; w++) tot += s_red[w];
            g_part[bid * 5 + s] = (double)tot;
        }
        __syncthreads();
    }

    // ================= completion ticket; last block finalizes ===============
    __threadfence();
    if (tid == 0) s_ticket = atomicAdd(&g_done, 1u);
    __syncthreads();

    if (s_ticket == gridDim.x - 1) {
        __threadfence();
        double v0 = 0, v1 = 0, v2 = 0, v3 = 0, v4 = 0;
        for (int i = tid; i < GRID; i += TPB) {
            v0 += g_part[i * 5 + 0];
            v1 += g_part[i * 5 + 1];
            v2 += g_part[i * 5 + 2];
            v3 += g_part[i * 5 + 3];
            v4 += g_part[i * 5 + 4];
        }
        #pragma unroll
        for (int o = 16; o > 0; o >>= 1) {
            v0 += __shfl_xor_sync(0xffffffffu, v0, o);
            v1 += __shfl_xor_sync(0xffffffffu, v1, o);
            v2 += __shfl_xor_sync(0xffffffffu, v2, o);
            v3 += __shfl_xor_sync(0xffffffffu, v3, o);
            v4 += __shfl_xor_sync(0xffffffffu, v4, o);
        }
        __shared__ double s_d[TPB / 32][5];
        if (lane == 0) {
            s_d[warp][0] = v0; s_d[warp][1] = v1; s_d[warp][2] = v2;
            s_d[warp][3] = v3; s_d[warp][4] = v4;
        }
        __syncthreads();
        if (tid == 0) {
            double f[5] = {0, 0, 0, 0, 0};
            for (int w = 0; w < TPB / 32; w++)
                for (int s = 0; s < 5; s++) f[s] += s_d[w][s];

            const double N = (double)NPIX, S = 1e-6;
            double ce       = f[0] / N;
            double dice     = 1.0 - (2.0 * f[3] + S) / (f[1] + f[2] + S);
            double boundary = f[4] / N;
            double total    = ce + dice + 0.1 * boundary;

            float vals[4] = { (float)total, (float)ce, (float)dice, (float)boundary };
            for (int i = 0; i < out_size && i < 4; i++) out[i] = vals[i];

            // reset persistent state for the next graph replay
            g_bar0 = 0;
            g_done = 0;
            for (int b = 0; b < BB; b++) g_nonempty[b] = 0;
        }
    }
}

extern "C" void kernel_launch(void* const* d_in, const int* in_sizes, int n_in,
                              void* d_out, int out_size) {
    const float* logits = (const float*)d_in[0];
    const float* target = (const float*)d_in[1];
    (void)in_sizes; (void)n_in;
    fused_loss_kernel<<<GRID, TPB>>>(logits, target, (float*)d_out, out_size);
}

// round 6
// speedup vs baseline: 2.1753x; 1.8063x over previous
#include <cuda_runtime.h>
#include <math.h>

// Problem shape (fixed by setup_inputs)
#define BB   8
#define HH   256
#define WW   256
#define NPIX (BB * HH * WW)
#define GRID 296          // 148 SMs x 2 blocks, all co-resident (verified R4)
#define TPB  256

// Persistent scratch. Counters/flags reset by the finalizer each launch.
__device__ float    g_g2[NPIX];        // squared vertical distance
__device__ int      g_nonempty[BB];
__device__ unsigned g_bar0;            // grid barrier counter
__device__ unsigned g_done;            // completion ticket
__device__ double   g_part[GRID * 5];  // per-block partial sums

__device__ __forceinline__ float warp_sum_f(float v) {
    #pragma unroll
    for (int o = 16; o > 0; o >>= 1) v += __shfl_xor_sync(0xffffffffu, v, o);
    return v;
}

__global__ void __launch_bounds__(TPB, 2)
fused_loss_kernel(const float* __restrict__ logits,
                  const float* __restrict__ target,
                  float* __restrict__ out, int out_size)
{
    const int tid  = threadIdx.x;
    const int bid  = blockIdx.x;
    const int lane = tid & 31, warp = tid >> 5;

    __shared__ float    s_g2[WW];
    __shared__ float    s_sqrt[128];
    __shared__ float    s_red[TPB / 32];
    __shared__ unsigned s_mask[8][32];   // phase-1 per-chunk fg masks
    __shared__ unsigned s_ticket;

    if (tid < 128) s_sqrt[tid] = sqrtf((float)tid);

    // ============ phase 1: vertical EDT, two-level bitmask scan =============
    // Blocks 0..63: block = (batch b, 32-column group). warp = 32-row chunk,
    // lane = column. All loads/stores warp-coalesced; depth 32 instead of 512.
    if (bid < 64) {
        int b    = bid >> 3;
        int col  = ((bid & 7) << 5) + lane;
        int r0   = warp << 5;
        const float* tp = target + b * HH * WW + col;

        unsigned mask = 0;                      // bit i = fg at row r0+i
        #pragma unroll
        for (int i = 0; i < 32; i++) {
            float tv = tp[(r0 + i) * WW];       // 32 independent loads (MLP=32)
            if (tv > 0.5f) mask |= (1u << i);
        }
        s_mask[warp][lane] = mask;
        __syncthreads();

        // forward carry: distance-so-far entering this chunk (init INF=512)
        int cin = 512;
        #pragma unroll
        for (int wp = 0; wp < 7; wp++) {
            if (wp < warp) {
                unsigned m = s_mask[wp][lane];
                cin = m ? __clz((int)m) : cin + 32;   // clz = dist from chunk end
            }
        }
        int f[32];
        int d = cin;
        #pragma unroll
        for (int i = 0; i < 32; i++) {
            d = ((mask >> i) & 1u) ? 0 : d + 1;
            f[i] = d;
        }

        // backward carry: distance entering from below
        int cbk = 512;
        #pragma unroll
        for (int wp = 7; wp >= 1; wp--) {
            if (wp > warp) {
                unsigned m = s_mask[wp][lane];
                cbk = m ? (__ffs((int)m) - 1) : cbk + 32;
            }
        }
        d = cbk;
        float* gp = g_g2 + b * HH * WW + col;
        #pragma unroll
        for (int i = 31; i >= 0; i--) {
            d = ((mask >> i) & 1u) ? 0 : d + 1;
            int g = min(f[i], d);
            gp[(r0 + i) * WW] = (float)(g * g);
        }

        if (__any_sync(0xffffffffu, mask != 0u) && lane == 0)
            g_nonempty[b] = 1;                  // benign same-value race
    }

    // ================= grid barrier (all 296 blocks resident) ================
    __syncthreads();
    __threadfence();
    if (tid == 0) {
        atomicAdd(&g_bar0, 1u);
        while (atomicAdd(&g_bar0, 0u) < gridDim.x) __nanosleep(64);
    }
    __syncthreads();
    __threadfence();

    // ============ phase 2: exact horizontal EDT + fused loss ================
    float acc0 = 0.f, acc1 = 0.f, acc2 = 0.f, acc3 = 0.f, acc4 = 0.f;

    for (int rt = bid; rt < BB * HH; rt += gridDim.x) {
        int b    = rt >> 8;
        int base = rt * WW;

        // prefetch everything for this row (MLP=3)
        float g2v = g_g2[base + tid];
        float x   = logits[base + tid];
        float t   = target[base + tid];
        s_g2[tid] = g2v;
        int ne = g_nonempty[b];
        __syncthreads();

        float dt = 0.0f;
        if (ne) {
            // exact EDT: widen until off^2 >= best (terms only grow)
            float best = g2v;
            int off = 1;
            float o2 = 1.0f;
            while (o2 < best) {
                int l = tid - off, r = tid + off;
                if (l >= 0) best = fminf(best, o2 + s_g2[l]);
                if (r < WW) best = fminf(best, o2 + s_g2[r]);
                off++;
                o2 = (float)(off * off);
            }
            dt = (best < 128.0f) ? s_sqrt[(int)best] : sqrtf(best);
        }

        t = fminf(fmaxf(t, 0.0f), 1.0f);

        // 2 MUFU per pixel: tanh + lg2
        float th;
        asm("tanh.approx.f32 %0, %1;" : "=f"(th) : "f"(0.5f * x));
        float h = 0.5f * th;                 // sigmoid(x) = 0.5 + h
        float p = 0.5f + h;
        p = fminf(fmaxf(p, 1e-6f), 1.0f - 1e-6f);
        float r = 0.5f + fabsf(h);           // sigmoid(|x|)
        // log1p(e^{-|x|}) = -ln(sigmoid(|x|)) = -ln2 * log2(r)
        float ce = fmaxf(x, 0.0f) - 0.69314718055994531f * __log2f(r) - x * t;

        acc0 += ce; acc1 += p; acc2 += t; acc3 += p * t; acc4 += p * dt;
        __syncthreads();
    }

    // ============ per-block reduction -> g_part (deterministic) =============
    float accs[5] = { acc0, acc1, acc2, acc3, acc4 };
    #pragma unroll
    for (int s = 0; s < 5; s++) {
        float v = warp_sum_f(accs[s]);
        if (lane == 0) s_red[warp] = v;
        __syncthreads();
        if (tid == 0) {
            float tot = 0.f;
            #pragma unroll
            for (int w = 0; w < TPB / 32; w++) tot += s_red[w];
            g_part[bid * 5 + s] = (double)tot;
        }
        __syncthreads();
    }

    // ============ completion ticket; last block finalizes ===================
    __threadfence();
    if (tid == 0) s_ticket = atomicAdd(&g_done, 1u);
    __syncthreads();

    if (s_ticket == gridDim.x - 1) {
        __threadfence();
        double v0 = 0, v1 = 0, v2 = 0, v3 = 0, v4 = 0;
        for (int i = tid; i < GRID; i += TPB) {
            v0 += g_part[i * 5 + 0];
            v1 += g_part[i * 5 + 1];
            v2 += g_part[i * 5 + 2];
            v3 += g_part[i * 5 + 3];
            v4 += g_part[i * 5 + 4];
        }
        #pragma unroll
        for (int o = 16; o > 0; o >>= 1) {
            v0 += __shfl_xor_sync(0xffffffffu, v0, o);
            v1 += __shfl_xor_sync(0xffffffffu, v1, o);
            v2 += __shfl_xor_sync(0xffffffffu, v2, o);
            v3 += __shfl_xor_sync(0xffffffffu, v3, o);
            v4 += __shfl_xor_sync(0xffffffffu, v4, o);
        }
        __shared__ double s_d[TPB / 32][5];
        if (lane == 0) {
            s_d[warp][0] = v0; s_d[warp][1] = v1; s_d[warp][2] = v2;
            s_d[warp][3] = v3; s_d[warp][4] = v4;
        }
        __syncthreads();
        if (tid == 0) {
            double fsum[5] = {0, 0, 0, 0, 0};
            for (int w = 0; w < TPB / 32; w++)
                for (int s = 0; s < 5; s++) fsum[s] += s_d[w][s];

            const double N = (double)NPIX, S = 1e-6;
            double ce       = fsum[0] / N;
            double dice     = 1.0 - (2.0 * fsum[3] + S) / (fsum[1] + fsum[2] + S);
            double boundary = fsum[4] / N;
            double total    = ce + dice + 0.1 * boundary;

            float vals[4] = { (float)total, (float)ce, (float)dice, (float)boundary };
            for (int i = 0; i < out_size && i < 4; i++) out[i] = vals[i];

            // reset persistent state for next graph replay
            g_bar0 = 0;
            g_done = 0;
            for (int b = 0; b < BB; b++) g_nonempty[b] = 0;
        }
    }
}

extern "C" void kernel_launch(void* const* d_in, const int* in_sizes, int n_in,
                              void* d_out, int out_size) {
    const float* logits = (const float*)d_in[0];
    const float* target = (const float*)d_in[1];
    (void)in_sizes; (void)n_in;
    fused_loss_kernel<<<GRID, TPB>>>(logits, target, (float*)d_out, out_size);
}